// round 1
// baseline (speedup 1.0000x reference)
#include <cuda_runtime.h>

#define NB 64
#define LC 4096
#define HD 768
#define PD 128
#define BUDGETF 200.0f

// Scratch (allocation-free rule: __device__ globals)
__device__ float d_U[NB * HD];      // u_b = Wc @ q_b
__device__ float d_qbias[NB];       // q_b . bc
__device__ float d_s[NB * LC];      // masked match scores

// ---------------------------------------------------------------------------
// Kernel 1: q_b = question[b] @ Wq + bq ; u_b = Wc @ q_b ; qbias = q_b . bc
// ---------------------------------------------------------------------------
__global__ void proj_kernel(const float* __restrict__ qr,
                            const float* __restrict__ Wq,
                            const float* __restrict__ bq,
                            const float* __restrict__ Wc,
                            const float* __restrict__ bc) {
    int b = blockIdx.x;
    __shared__ float sh_qr[HD];
    __shared__ float sh_q[PD];
    int tid = threadIdx.x;  // 256

    for (int i = tid; i < HD; i += blockDim.x) sh_qr[i] = qr[b * HD + i];
    __syncthreads();

    if (tid < PD) {
        float acc = bq[tid];
        #pragma unroll 8
        for (int h = 0; h < HD; h++) acc = fmaf(sh_qr[h], Wq[h * PD + tid], acc);
        sh_q[tid] = acc;
    }
    __syncthreads();

    for (int h = tid; h < HD; h += blockDim.x) {
        const float* wr = Wc + h * PD;
        float acc = 0.f;
        #pragma unroll 8
        for (int p = 0; p < PD; p++) acc = fmaf(wr[p], sh_q[p], acc);
        d_U[b * HD + h] = acc;
    }

    if (tid == 0) {
        float acc = 0.f;
        for (int p = 0; p < PD; p++) acc = fmaf(sh_q[p], bc[p], acc);
        d_qbias[b] = acc;
    }
}

// ---------------------------------------------------------------------------
// Kernel 2: s[b,j] = ctx[b,j,:] . u_b + qbias   (valid rows),  -1e5 (masked)
// Memory-bound streaming kernel. One warp per row, float4 loads, mask-skip.
// ---------------------------------------------------------------------------
__global__ void __launch_bounds__(256) score_kernel(const float* __restrict__ ctx,
                                                    const int* __restrict__ mask) {
    int b = blockIdx.y;
    int j0 = blockIdx.x * 128;          // 128 rows per block, 32 blocks per batch
    __shared__ float sh_u[HD];
    int tid = threadIdx.x;              // 256
    for (int i = tid; i < HD; i += 256) sh_u[i] = d_U[b * HD + i];
    __syncthreads();

    float bias = d_qbias[b];
    int warp = tid >> 5, lane = tid & 31;
    const float4* u4 = (const float4*)sh_u;

    for (int r = warp; r < 128; r += 8) {
        int j = j0 + r;
        if (mask[b * LC + j] == 0) {
            if (lane == 0) d_s[b * LC + j] = -100000.0f;
            continue;
        }
        const float4* row = (const float4*)(ctx + ((size_t)b * LC + j) * HD);
        float acc = 0.f;
        #pragma unroll
        for (int i = 0; i < 6; i++) {        // 192 float4 per row / 32 lanes
            float4 v = row[lane + 32 * i];
            float4 w = u4[lane + 32 * i];
            acc = fmaf(v.x, w.x, acc);
            acc = fmaf(v.y, w.y, acc);
            acc = fmaf(v.z, w.z, acc);
            acc = fmaf(v.w, w.w, acc);
        }
        #pragma unroll
        for (int off = 16; off; off >>= 1)
            acc += __shfl_xor_sync(0xffffffffu, acc, off);
        if (lane == 0) d_s[b * LC + j] = acc + bias;   // mask==1 -> penalty 0
    }
}

// ---------------------------------------------------------------------------
// Kernel 3: per-batch budget projection (bisection on tau) + token scatter
// ---------------------------------------------------------------------------
__device__ __forceinline__ float clip01(float v) {
    return fminf(fmaxf(v, 0.f), 1.f);
}

__device__ float block_reduce_sum(float v, float* redbuf, float* bcast) {
    int tid = threadIdx.x, warp = tid >> 5, lane = tid & 31;
    #pragma unroll
    for (int off = 16; off; off >>= 1) v += __shfl_xor_sync(0xffffffffu, v, off);
    if (lane == 0) redbuf[warp] = v;
    __syncthreads();
    if (warp == 0) {
        float x = (lane < 16) ? redbuf[lane] : 0.f;
        #pragma unroll
        for (int off = 8; off; off >>= 1) x += __shfl_xor_sync(0xffffffffu, x, off);
        if (lane == 0) *bcast = x;
    }
    __syncthreads();
    return *bcast;
}

__device__ float block_reduce_max(float v, float* redbuf, float* bcast) {
    int tid = threadIdx.x, warp = tid >> 5, lane = tid & 31;
    #pragma unroll
    for (int off = 16; off; off >>= 1)
        v = fmaxf(v, __shfl_xor_sync(0xffffffffu, v, off));
    if (lane == 0) redbuf[warp] = v;
    __syncthreads();
    if (warp == 0) {
        float x = (lane < 16) ? redbuf[lane] : -3.402823e38f;
        #pragma unroll
        for (int off = 8; off; off >>= 1)
            x = fmaxf(x, __shfl_xor_sync(0xffffffffu, x, off));
        if (lane == 0) *bcast = x;
    }
    __syncthreads();
    return *bcast;
}

__global__ void __launch_bounds__(512) budget_kernel(const int* __restrict__ mask,
                                                     const int* __restrict__ qe_arr,
                                                     float* __restrict__ out) {
    int b = blockIdx.x;
    const int NT = 512;
    __shared__ float sh_s[LC];
    __shared__ float redf[16];
    __shared__ float sh_bc;
    int tid = threadIdx.x;

    // load s into smem
    const float4* src = (const float4*)(d_s + b * LC);
    for (int i = tid; i < LC / 4; i += NT) ((float4*)sh_s)[i] = src[i];

    // count valid tokens
    float cnt = 0.f;
    for (int i = tid; i < LC; i += NT) cnt += (float)mask[b * LC + i];
    __syncthreads();

    // local max and z_sum(0)
    float mx = -3.402823e38f, sum0 = 0.f;
    for (int i = tid; i < LC; i += NT) {
        float v = sh_s[i];
        mx = fmaxf(mx, v);
        sum0 += clip01(v);
    }

    float cnt_tot = block_reduce_sum(cnt, redf, &sh_bc);
    float mx_tot  = block_reduce_max(mx, redf, &sh_bc);
    float sum0_tot = block_reduce_sum(sum0, redf, &sh_bc);

    float tau = 0.f;
    if (sum0_tot > BUDGETF) {
        // bisection on [0, max(s)] — converges to same tau as reference's
        // [min-1, max] bracket since tau* > 0 when constraint is active.
        float lo = 0.f, hi = mx_tot;
        for (int it = 0; it < 48; it++) {
            float mid = 0.5f * (lo + hi);
            float part = 0.f;
            for (int i = tid; i < LC; i += NT) part += clip01(sh_s[i] - mid);
            float tot = block_reduce_sum(part, redf, &sh_bc);
            if (tot > BUDGETF) lo = mid; else hi = mid;
        }
        tau = 0.5f * (lo + hi);
    }

    // fused gather/scatter into token_z
    int qe = qe_arr[b];
    int clen = (int)cnt_tot - 1;
    for (int p = tid; p < LC; p += NT) {
        float v;
        if (p < qe) {
            v = 1.f;
        } else {
            int idx = p - qe + 1;                 // >= 1 here
            v = (idx <= clen) ? clip01(sh_s[idx] - tau) : 0.f;
        }
        out[b * LC + p] = v;
    }
}

// ---------------------------------------------------------------------------
extern "C" void kernel_launch(void* const* d_in, const int* in_sizes, int n_in,
                              void* d_out, int out_size) {
    const float* question = (const float*)d_in[0];  // [B,1,H]
    const float* context  = (const float*)d_in[1];  // [B,LC,H]
    const float* Wq       = (const float*)d_in[2];  // [H,P]
    const float* bq       = (const float*)d_in[3];  // [P]
    const float* Wc       = (const float*)d_in[4];  // [H,P]
    const float* bc       = (const float*)d_in[5];  // [P]
    const int*   maskp    = (const int*)d_in[6];    // [B,LC]
    const int*   qep      = (const int*)d_in[7];    // [B]
    float* out = (float*)d_out;                     // [B,MAXLEN]

    proj_kernel<<<NB, 256>>>(question, Wq, bq, Wc, bc);
    dim3 g2(LC / 128, NB);
    score_kernel<<<g2, 256>>>(context, maskp);
    budget_kernel<<<NB, 512>>>(maskp, qep, out);
}

// round 2
// speedup vs baseline: 1.5436x; 1.5436x over previous
#include <cuda_runtime.h>

#define NB 64
#define LC 4096
#define HD 768
#define PD 128
#define BUDGETF 200.0f

// Scratch (allocation-free rule: __device__ globals)
__device__ float d_q[NB * PD];      // q_b = qr_b @ Wq + bq
__device__ float d_U[NB * HD];      // u_b = Wc @ q_b
__device__ float d_qbias[NB];       // q_b . bc
__device__ float d_s[NB * LC];      // masked match scores

// ---------------------------------------------------------------------------
// Kernel 1a: q[b,p] = qr[b,:] . Wq[:,p] + bq[p]  ;  qbias[b] = q_b . bc
// 512 threads: 4 h-slices x 128 p. Coalesced Wq reads, chain split 4x.
// ---------------------------------------------------------------------------
__global__ void __launch_bounds__(512) qproj_kernel(const float* __restrict__ qr,
                                                    const float* __restrict__ Wq,
                                                    const float* __restrict__ bq,
                                                    const float* __restrict__ bc) {
    int b = blockIdx.x;
    __shared__ float sh_qr[HD];
    __shared__ float sh_part[512];
    int tid = threadIdx.x;

    for (int i = tid; i < HD; i += 512) sh_qr[i] = qr[b * HD + i];
    __syncthreads();

    int p = tid & 127;
    int slice = tid >> 7;            // 0..3
    int h0 = slice * (HD / 4);       // 192 rows per slice
    float a0 = 0.f, a1 = 0.f, a2 = 0.f, a3 = 0.f;
    #pragma unroll 4
    for (int h = h0; h < h0 + HD / 4; h += 4) {
        a0 = fmaf(sh_qr[h + 0], Wq[(h + 0) * PD + p], a0);
        a1 = fmaf(sh_qr[h + 1], Wq[(h + 1) * PD + p], a1);
        a2 = fmaf(sh_qr[h + 2], Wq[(h + 2) * PD + p], a2);
        a3 = fmaf(sh_qr[h + 3], Wq[(h + 3) * PD + p], a3);
    }
    sh_part[tid] = (a0 + a1) + (a2 + a3);
    __syncthreads();

    if (tid < PD) {
        float q = sh_part[tid] + sh_part[PD + tid] + sh_part[2 * PD + tid]
                + sh_part[3 * PD + tid] + bq[tid];
        d_q[b * PD + tid] = q;
        sh_part[tid] = q;
    }
    __syncthreads();

    if (tid < 32) {
        float v = 0.f;
        #pragma unroll
        for (int k = 0; k < 4; k++)
            v = fmaf(sh_part[tid + 32 * k], bc[tid + 32 * k], v);
        #pragma unroll
        for (int off = 16; off; off >>= 1)
            v += __shfl_xor_sync(0xffffffffu, v, off);
        if (tid == 0) d_qbias[b] = v;
    }
}

// ---------------------------------------------------------------------------
// Kernel 1b: u[b,h] = Wc[h,:] . q_b   (warp per h, lanes over p: coalesced)
// grid (64, 4) = 256 blocks to fill the chip.
// ---------------------------------------------------------------------------
__global__ void __launch_bounds__(256) uproj_kernel(const float* __restrict__ Wc) {
    int b = blockIdx.x;
    int chunk = blockIdx.y;
    __shared__ float sh_q[PD];
    int tid = threadIdx.x;
    if (tid < PD) sh_q[tid] = d_q[b * PD + tid];
    __syncthreads();

    int warp = tid >> 5, lane = tid & 31;
    for (int hh = warp; hh < HD / 4; hh += 8) {
        int h = chunk * (HD / 4) + hh;
        const float* wr = Wc + (size_t)h * PD;
        float acc = wr[lane] * sh_q[lane];
        acc = fmaf(wr[lane + 32], sh_q[lane + 32], acc);
        acc = fmaf(wr[lane + 64], sh_q[lane + 64], acc);
        acc = fmaf(wr[lane + 96], sh_q[lane + 96], acc);
        #pragma unroll
        for (int off = 16; off; off >>= 1)
            acc += __shfl_xor_sync(0xffffffffu, acc, off);
        if (lane == 0) d_U[b * HD + h] = acc;
    }
}

// ---------------------------------------------------------------------------
// Kernel 2: s[b,j] = ctx[b,j,:] . u_b + qbias (valid), -1e5 (masked)
// ---------------------------------------------------------------------------
__global__ void __launch_bounds__(256) score_kernel(const float* __restrict__ ctx,
                                                    const int* __restrict__ mask) {
    int b = blockIdx.y;
    int j0 = blockIdx.x * 128;
    __shared__ float sh_u[HD];
    int tid = threadIdx.x;
    for (int i = tid; i < HD; i += 256) sh_u[i] = d_U[b * HD + i];
    __syncthreads();

    float bias = d_qbias[b];
    int warp = tid >> 5, lane = tid & 31;
    const float4* u4 = (const float4*)sh_u;

    for (int r = warp; r < 128; r += 8) {
        int j = j0 + r;
        if (mask[b * LC + j] == 0) {
            if (lane == 0) d_s[b * LC + j] = -100000.0f;
            continue;
        }
        const float4* row = (const float4*)(ctx + ((size_t)b * LC + j) * HD);
        float acc = 0.f;
        #pragma unroll
        for (int i = 0; i < 6; i++) {
            float4 v = row[lane + 32 * i];
            float4 w = u4[lane + 32 * i];
            acc = fmaf(v.x, w.x, acc);
            acc = fmaf(v.y, w.y, acc);
            acc = fmaf(v.z, w.z, acc);
            acc = fmaf(v.w, w.w, acc);
        }
        #pragma unroll
        for (int off = 16; off; off >>= 1)
            acc += __shfl_xor_sync(0xffffffffu, acc, off);
        if (lane == 0) d_s[b * LC + j] = acc + bias;
    }
}

// ---------------------------------------------------------------------------
// Kernel 3: per-batch budget projection (bisection on tau) + token scatter
// ---------------------------------------------------------------------------
__device__ __forceinline__ float clip01(float v) {
    return fminf(fmaxf(v, 0.f), 1.f);
}

__device__ float block_reduce_sum(float v, float* redbuf, float* bcast) {
    int tid = threadIdx.x, warp = tid >> 5, lane = tid & 31;
    #pragma unroll
    for (int off = 16; off; off >>= 1) v += __shfl_xor_sync(0xffffffffu, v, off);
    if (lane == 0) redbuf[warp] = v;
    __syncthreads();
    if (warp == 0) {
        float x = (lane < 16) ? redbuf[lane] : 0.f;
        #pragma unroll
        for (int off = 8; off; off >>= 1) x += __shfl_xor_sync(0xffffffffu, x, off);
        if (lane == 0) *bcast = x;
    }
    __syncthreads();
    return *bcast;
}

__device__ float block_reduce_max(float v, float* redbuf, float* bcast) {
    int tid = threadIdx.x, warp = tid >> 5, lane = tid & 31;
    #pragma unroll
    for (int off = 16; off; off >>= 1)
        v = fmaxf(v, __shfl_xor_sync(0xffffffffu, v, off));
    if (lane == 0) redbuf[warp] = v;
    __syncthreads();
    if (warp == 0) {
        float x = (lane < 16) ? redbuf[lane] : -3.402823e38f;
        #pragma unroll
        for (int off = 8; off; off >>= 1)
            x = fmaxf(x, __shfl_xor_sync(0xffffffffu, x, off));
        if (lane == 0) *bcast = x;
    }
    __syncthreads();
    return *bcast;
}

__global__ void __launch_bounds__(512) budget_kernel(const int* __restrict__ mask,
                                                     const int* __restrict__ qe_arr,
                                                     float* __restrict__ out) {
    int b = blockIdx.x;
    const int NT = 512;
    __shared__ float sh_s[LC];
    __shared__ float redf[16];
    __shared__ float sh_bc;
    int tid = threadIdx.x;

    const float4* src = (const float4*)(d_s + b * LC);
    for (int i = tid; i < LC / 4; i += NT) ((float4*)sh_s)[i] = src[i];

    float cnt = 0.f;
    for (int i = tid; i < LC; i += NT) cnt += (float)mask[b * LC + i];
    __syncthreads();

    float mx = -3.402823e38f, sum0 = 0.f;
    for (int i = tid; i < LC; i += NT) {
        float v = sh_s[i];
        mx = fmaxf(mx, v);
        sum0 += clip01(v);
    }

    float cnt_tot  = block_reduce_sum(cnt, redf, &sh_bc);
    float mx_tot   = block_reduce_max(mx, redf, &sh_bc);
    float sum0_tot = block_reduce_sum(sum0, redf, &sh_bc);

    float tau = 0.f;
    if (sum0_tot > BUDGETF) {
        float lo = 0.f, hi = mx_tot;
        for (int it = 0; it < 48; it++) {
            float mid = 0.5f * (lo + hi);
            float part = 0.f;
            for (int i = tid; i < LC; i += NT) part += clip01(sh_s[i] - mid);
            float tot = block_reduce_sum(part, redf, &sh_bc);
            if (tot > BUDGETF) lo = mid; else hi = mid;
        }
        tau = 0.5f * (lo + hi);
    }

    int qe = qe_arr[b];
    int clen = (int)cnt_tot - 1;
    for (int p = tid; p < LC; p += NT) {
        float v;
        if (p < qe) {
            v = 1.f;
        } else {
            int idx = p - qe + 1;
            v = (idx <= clen) ? clip01(sh_s[idx] - tau) : 0.f;
        }
        out[b * LC + p] = v;
    }
}

// ---------------------------------------------------------------------------
extern "C" void kernel_launch(void* const* d_in, const int* in_sizes, int n_in,
                              void* d_out, int out_size) {
    const float* question = (const float*)d_in[0];  // [B,1,H]
    const float* context  = (const float*)d_in[1];  // [B,LC,H]
    const float* Wq       = (const float*)d_in[2];  // [H,P]
    const float* bq       = (const float*)d_in[3];  // [P]
    const float* Wc       = (const float*)d_in[4];  // [H,P]
    const float* bc       = (const float*)d_in[5];  // [P]
    const int*   maskp    = (const int*)d_in[6];    // [B,LC]
    const int*   qep      = (const int*)d_in[7];    // [B]
    float* out = (float*)d_out;                     // [B,MAXLEN]

    qproj_kernel<<<NB, 512>>>(question, Wq, bq, bc);
    dim3 gu(NB, 4);
    uproj_kernel<<<gu, 256>>>(Wc);
    dim3 g2(LC / 128, NB);
    score_kernel<<<g2, 256>>>(context, maskp);
    budget_kernel<<<NB, 512>>>(maskp, qep, out);
}

// round 3
// speedup vs baseline: 1.5496x; 1.0039x over previous
#include <cuda_runtime.h>

#define NB 64
#define LC 4096
#define HD 768
#define PD 128
#define BUDGETF 200.0f

// Scratch (allocation-free rule: __device__ globals)
__device__ float d_q[NB * PD];      // q_b = qr_b @ Wq + bq
__device__ float d_U[NB * HD];      // u_b = Wc @ q_b
__device__ float d_qbias[NB];       // q_b . bc
__device__ float d_s[NB * LC];      // masked match scores

// ---------------------------------------------------------------------------
// Kernel 1a: q[b,p] = qr[b,:] . Wq[:,p] + bq[p]  ;  qbias[b] = q_b . bc
// 512 threads: 4 h-slices x 128 p. Coalesced Wq reads, chain split 4x.
// ---------------------------------------------------------------------------
__global__ void __launch_bounds__(512) qproj_kernel(const float* __restrict__ qr,
                                                    const float* __restrict__ Wq,
                                                    const float* __restrict__ bq,
                                                    const float* __restrict__ bc) {
    int b = blockIdx.x;
    __shared__ float sh_qr[HD];
    __shared__ float sh_part[512];
    int tid = threadIdx.x;

    for (int i = tid; i < HD; i += 512) sh_qr[i] = qr[b * HD + i];
    __syncthreads();

    int p = tid & 127;
    int slice = tid >> 7;            // 0..3
    int h0 = slice * (HD / 4);       // 192 rows per slice
    float a0 = 0.f, a1 = 0.f, a2 = 0.f, a3 = 0.f;
    #pragma unroll 4
    for (int h = h0; h < h0 + HD / 4; h += 4) {
        a0 = fmaf(sh_qr[h + 0], Wq[(h + 0) * PD + p], a0);
        a1 = fmaf(sh_qr[h + 1], Wq[(h + 1) * PD + p], a1);
        a2 = fmaf(sh_qr[h + 2], Wq[(h + 2) * PD + p], a2);
        a3 = fmaf(sh_qr[h + 3], Wq[(h + 3) * PD + p], a3);
    }
    sh_part[tid] = (a0 + a1) + (a2 + a3);
    __syncthreads();

    if (tid < PD) {
        float q = sh_part[tid] + sh_part[PD + tid] + sh_part[2 * PD + tid]
                + sh_part[3 * PD + tid] + bq[tid];
        d_q[b * PD + tid] = q;
        sh_part[tid] = q;
    }
    __syncthreads();

    if (tid < 32) {
        float v = 0.f;
        #pragma unroll
        for (int k = 0; k < 4; k++)
            v = fmaf(sh_part[tid + 32 * k], bc[tid + 32 * k], v);
        #pragma unroll
        for (int off = 16; off; off >>= 1)
            v += __shfl_xor_sync(0xffffffffu, v, off);
        if (tid == 0) d_qbias[b] = v;
    }
}

// ---------------------------------------------------------------------------
// Kernel 1b: u[b,h] = Wc[h,:] . q_b   (warp per h, lanes over p: coalesced)
// grid (64, 4) = 256 blocks to fill the chip.
// ---------------------------------------------------------------------------
__global__ void __launch_bounds__(256) uproj_kernel(const float* __restrict__ Wc) {
    int b = blockIdx.x;
    int chunk = blockIdx.y;
    __shared__ float sh_q[PD];
    int tid = threadIdx.x;
    if (tid < PD) sh_q[tid] = d_q[b * PD + tid];
    __syncthreads();

    int warp = tid >> 5, lane = tid & 31;
    for (int hh = warp; hh < HD / 4; hh += 8) {
        int h = chunk * (HD / 4) + hh;
        const float* wr = Wc + (size_t)h * PD;
        float acc = wr[lane] * sh_q[lane];
        acc = fmaf(wr[lane + 32], sh_q[lane + 32], acc);
        acc = fmaf(wr[lane + 64], sh_q[lane + 64], acc);
        acc = fmaf(wr[lane + 96], sh_q[lane + 96], acc);
        #pragma unroll
        for (int off = 16; off; off >>= 1)
            acc += __shfl_xor_sync(0xffffffffu, acc, off);
        if (lane == 0) d_U[b * HD + h] = acc;
    }
}

// ---------------------------------------------------------------------------
// Kernel 2: s[b,j] = ctx[b,j,:] . u_b + qbias (valid), -1e5 (masked)
// ---------------------------------------------------------------------------
__global__ void __launch_bounds__(256) score_kernel(const float* __restrict__ ctx,
                                                    const int* __restrict__ mask) {
    int b = blockIdx.y;
    int j0 = blockIdx.x * 128;
    __shared__ float sh_u[HD];
    int tid = threadIdx.x;
    for (int i = tid; i < HD; i += 256) sh_u[i] = d_U[b * HD + i];
    __syncthreads();

    float bias = d_qbias[b];
    int warp = tid >> 5, lane = tid & 31;
    const float4* u4 = (const float4*)sh_u;

    for (int r = warp; r < 128; r += 8) {
        int j = j0 + r;
        if (mask[b * LC + j] == 0) {
            if (lane == 0) d_s[b * LC + j] = -100000.0f;
            continue;
        }
        const float4* row = (const float4*)(ctx + ((size_t)b * LC + j) * HD);
        float acc = 0.f;
        #pragma unroll
        for (int i = 0; i < 6; i++) {
            float4 v = row[lane + 32 * i];
            float4 w = u4[lane + 32 * i];
            acc = fmaf(v.x, w.x, acc);
            acc = fmaf(v.y, w.y, acc);
            acc = fmaf(v.z, w.z, acc);
            acc = fmaf(v.w, w.w, acc);
        }
        #pragma unroll
        for (int off = 16; off; off >>= 1)
            acc += __shfl_xor_sync(0xffffffffu, acc, off);
        if (lane == 0) d_s[b * LC + j] = acc + bias;
    }
}

// ---------------------------------------------------------------------------
// Kernel 3: per-batch budget projection (bisection on tau) + token scatter
// ---------------------------------------------------------------------------
__device__ __forceinline__ float clip01(float v) {
    return fminf(fmaxf(v, 0.f), 1.f);
}

__device__ float block_reduce_sum(float v, float* redbuf, float* bcast) {
    int tid = threadIdx.x, warp = tid >> 5, lane = tid & 31;
    #pragma unroll
    for (int off = 16; off; off >>= 1) v += __shfl_xor_sync(0xffffffffu, v, off);
    if (lane == 0) redbuf[warp] = v;
    __syncthreads();
    if (warp == 0) {
        float x = (lane < 16) ? redbuf[lane] : 0.f;
        #pragma unroll
        for (int off = 8; off; off >>= 1) x += __shfl_xor_sync(0xffffffffu, x, off);
        if (lane == 0) *bcast = x;
    }
    __syncthreads();
    return *bcast;
}

__device__ float block_reduce_max(float v, float* redbuf, float* bcast) {
    int tid = threadIdx.x, warp = tid >> 5, lane = tid & 31;
    #pragma unroll
    for (int off = 16; off; off >>= 1)
        v = fmaxf(v, __shfl_xor_sync(0xffffffffu, v, off));
    if (lane == 0) redbuf[warp] = v;
    __syncthreads();
    if (warp == 0) {
        float x = (lane < 16) ? redbuf[lane] : -3.402823e38f;
        #pragma unroll
        for (int off = 8; off; off >>= 1)
            x = fmaxf(x, __shfl_xor_sync(0xffffffffu, x, off));
        if (lane == 0) *bcast = x;
    }
    __syncthreads();
    return *bcast;
}

__global__ void __launch_bounds__(512) budget_kernel(const int* __restrict__ mask,
                                                     const int* __restrict__ qe_arr,
                                                     float* __restrict__ out) {
    int b = blockIdx.x;
    const int NT = 512;
    __shared__ float sh_s[LC];
    __shared__ float redf[16];
    __shared__ float sh_bc;
    int tid = threadIdx.x;

    const float4* src = (const float4*)(d_s + b * LC);
    for (int i = tid; i < LC / 4; i += NT) ((float4*)sh_s)[i] = src[i];

    float cnt = 0.f;
    for (int i = tid; i < LC; i += NT) cnt += (float)mask[b * LC + i];
    __syncthreads();

    float mx = -3.402823e38f, sum0 = 0.f;
    for (int i = tid; i < LC; i += NT) {
        float v = sh_s[i];
        mx = fmaxf(mx, v);
        sum0 += clip01(v);
    }

    float cnt_tot  = block_reduce_sum(cnt, redf, &sh_bc);
    float mx_tot   = block_reduce_max(mx, redf, &sh_bc);
    float sum0_tot = block_reduce_sum(sum0, redf, &sh_bc);

    float tau = 0.f;
    if (sum0_tot > BUDGETF) {
        float lo = 0.f, hi = mx_tot;
        for (int it = 0; it < 48; it++) {
            float mid = 0.5f * (lo + hi);
            float part = 0.f;
            for (int i = tid; i < LC; i += NT) part += clip01(sh_s[i] - mid);
            float tot = block_reduce_sum(part, redf, &sh_bc);
            if (tot > BUDGETF) lo = mid; else hi = mid;
        }
        tau = 0.5f * (lo + hi);
    }

    int qe = qe_arr[b];
    int clen = (int)cnt_tot - 1;
    for (int p = tid; p < LC; p += NT) {
        float v;
        if (p < qe) {
            v = 1.f;
        } else {
            int idx = p - qe + 1;
            v = (idx <= clen) ? clip01(sh_s[idx] - tau) : 0.f;
        }
        out[b * LC + p] = v;
    }
}

// ---------------------------------------------------------------------------
extern "C" void kernel_launch(void* const* d_in, const int* in_sizes, int n_in,
                              void* d_out, int out_size) {
    const float* question = (const float*)d_in[0];  // [B,1,H]
    const float* context  = (const float*)d_in[1];  // [B,LC,H]
    const float* Wq       = (const float*)d_in[2];  // [H,P]
    const float* bq       = (const float*)d_in[3];  // [P]
    const float* Wc       = (const float*)d_in[4];  // [H,P]
    const float* bc       = (const float*)d_in[5];  // [P]
    const int*   maskp    = (const int*)d_in[6];    // [B,LC]
    const int*   qep      = (const int*)d_in[7];    // [B]
    float* out = (float*)d_out;                     // [B,MAXLEN]

    qproj_kernel<<<NB, 512>>>(question, Wq, bq, bc);
    dim3 gu(NB, 4);
    uproj_kernel<<<gu, 256>>>(Wc);
    dim3 g2(LC / 128, NB);
    score_kernel<<<g2, 256>>>(context, maskp);
    budget_kernel<<<NB, 512>>>(maskp, qep, out);
}

// round 4
// speedup vs baseline: 1.8703x; 1.2069x over previous
#include <cuda_runtime.h>

#define NB 64
#define LC 4096
#define HD 768
#define PD 128
#define BUDGETF 200.0f
#define NCHUNK 32                 // LC / 128 chunks per batch

// Scratch (allocation-free rule: __device__ globals)
__device__ float d_q[NB * PD];      // q_b = qr_b @ Wq + bq
__device__ float d_U[NB * HD];      // u_b = Wc @ q_b
__device__ float d_qbias[NB];       // q_b . bc
__device__ int   d_len[NB];         // valid context length per batch
__device__ float d_s[NB * LC];      // match scores (only [0,len) valid)

// ---------------------------------------------------------------------------
// Kernel 1a: q[b,p] = qr[b,:] . Wq[:,p] + bq[p] ; qbias[b] = q_b . bc ;
//            len[b] = sum(mask[b,:])
// ---------------------------------------------------------------------------
__global__ void __launch_bounds__(512) qproj_kernel(const float* __restrict__ qr,
                                                    const float* __restrict__ Wq,
                                                    const float* __restrict__ bq,
                                                    const float* __restrict__ bc,
                                                    const int* __restrict__ mask) {
    int b = blockIdx.x;
    __shared__ float sh_qr[HD];
    __shared__ float sh_part[512];
    __shared__ int sh_cnt[16];
    int tid = threadIdx.x;

    for (int i = tid; i < HD; i += 512) sh_qr[i] = qr[b * HD + i];

    // mask count (overlaps with GEMV nicely)
    int cnt = 0;
    for (int i = tid; i < LC; i += 512) cnt += mask[b * LC + i];
    #pragma unroll
    for (int off = 16; off; off >>= 1) cnt += __shfl_xor_sync(0xffffffffu, cnt, off);
    if ((tid & 31) == 0) sh_cnt[tid >> 5] = cnt;
    __syncthreads();
    if (tid == 0) {
        int t = 0;
        #pragma unroll
        for (int w = 0; w < 16; w++) t += sh_cnt[w];
        d_len[b] = t;
    }

    int p = tid & 127;
    int slice = tid >> 7;            // 0..3
    int h0 = slice * (HD / 4);       // 192 rows per slice
    float a0 = 0.f, a1 = 0.f, a2 = 0.f, a3 = 0.f;
    #pragma unroll 4
    for (int h = h0; h < h0 + HD / 4; h += 4) {
        a0 = fmaf(sh_qr[h + 0], Wq[(h + 0) * PD + p], a0);
        a1 = fmaf(sh_qr[h + 1], Wq[(h + 1) * PD + p], a1);
        a2 = fmaf(sh_qr[h + 2], Wq[(h + 2) * PD + p], a2);
        a3 = fmaf(sh_qr[h + 3], Wq[(h + 3) * PD + p], a3);
    }
    sh_part[tid] = (a0 + a1) + (a2 + a3);
    __syncthreads();

    if (tid < PD) {
        float q = sh_part[tid] + sh_part[PD + tid] + sh_part[2 * PD + tid]
                + sh_part[3 * PD + tid] + bq[tid];
        d_q[b * PD + tid] = q;
        sh_part[tid] = q;
    }
    __syncthreads();

    if (tid < 32) {
        float v = 0.f;
        #pragma unroll
        for (int k = 0; k < 4; k++)
            v = fmaf(sh_part[tid + 32 * k], bc[tid + 32 * k], v);
        #pragma unroll
        for (int off = 16; off; off >>= 1)
            v += __shfl_xor_sync(0xffffffffu, v, off);
        if (tid == 0) d_qbias[b] = v;
    }
}

// ---------------------------------------------------------------------------
// Kernel 1b: u[b,h] = Wc[h,:] . q_b   (warp per h, lanes over p: coalesced)
// ---------------------------------------------------------------------------
__global__ void __launch_bounds__(256) uproj_kernel(const float* __restrict__ Wc) {
    int b = blockIdx.x;
    int chunk = blockIdx.y;
    __shared__ float sh_q[PD];
    int tid = threadIdx.x;
    if (tid < PD) sh_q[tid] = d_q[b * PD + tid];
    __syncthreads();

    int warp = tid >> 5, lane = tid & 31;
    for (int hh = warp; hh < HD / 4; hh += 8) {
        int h = chunk * (HD / 4) + hh;
        const float* wr = Wc + (size_t)h * PD;
        float acc = wr[lane] * sh_q[lane];
        acc = fmaf(wr[lane + 32], sh_q[lane + 32], acc);
        acc = fmaf(wr[lane + 64], sh_q[lane + 64], acc);
        acc = fmaf(wr[lane + 96], sh_q[lane + 96], acc);
        #pragma unroll
        for (int off = 16; off; off >>= 1)
            acc += __shfl_xor_sync(0xffffffffu, acc, off);
        if (lane == 0) d_U[b * HD + h] = acc;
    }
}

// ---------------------------------------------------------------------------
// Kernel 2: s[b,j] = ctx[b,j,:].u_b + qbias for j < len[b].
// Grid-stride persistent blocks over (b, chunk) pairs; no mask reads,
// invalid rows never touched. Streaming (__ldcs) context loads.
// ---------------------------------------------------------------------------
#define SCORE_BLOCKS 1184

__global__ void __launch_bounds__(256) score_kernel(const float* __restrict__ ctx) {
    __shared__ float sh_u[HD];
    int tid = threadIdx.x;
    int warp = tid >> 5, lane = tid & 31;

    for (int c = blockIdx.x; c < NB * NCHUNK; c += gridDim.x) {
        int b = c >> 5;                 // NCHUNK = 32
        int j0 = (c & 31) * 128;
        int len = d_len[b];
        if (j0 >= len) continue;        // uniform across block

        __syncthreads();                // protect sh_u from previous iteration
        for (int i = tid; i < HD; i += 256) sh_u[i] = d_U[b * HD + i];
        __syncthreads();

        int nv = min(128, len - j0);
        float bias = d_qbias[b];
        const float4* u4 = (const float4*)sh_u;

        for (int r = warp; r < nv; r += 8) {
            int j = j0 + r;
            const float4* row = (const float4*)(ctx + ((size_t)b * LC + j) * HD);
            float acc = 0.f;
            #pragma unroll
            for (int i = 0; i < 6; i++) {       // 192 float4 / 32 lanes
                float4 v = __ldcs(row + lane + 32 * i);
                float4 w = u4[lane + 32 * i];
                acc = fmaf(v.x, w.x, acc);
                acc = fmaf(v.y, w.y, acc);
                acc = fmaf(v.z, w.z, acc);
                acc = fmaf(v.w, w.w, acc);
            }
            #pragma unroll
            for (int off = 16; off; off >>= 1)
                acc += __shfl_xor_sync(0xffffffffu, acc, off);
            if (lane == 0) d_s[b * LC + j] = acc + bias;
        }
    }
}

// ---------------------------------------------------------------------------
// Kernel 3: per-batch budget projection (register-resident bisection) + scatter
// 256 threads x 16 values in registers.
// ---------------------------------------------------------------------------
__device__ __forceinline__ float clip01(float v) {
    return fminf(fmaxf(v, 0.f), 1.f);
}

__global__ void __launch_bounds__(256) budget_kernel(const int* __restrict__ qe_arr,
                                                     float* __restrict__ out) {
    int b = blockIdx.x;
    const int NT = 256;
    __shared__ float sh_s[LC];
    __shared__ float redf[8];
    __shared__ float sh_bc;
    int tid = threadIdx.x, warp = tid >> 5, lane = tid & 31;
    int len = d_len[b];

    // load s into smem (gather needs random access) — full copy, garbage
    // beyond len is never read (gather idx <= len-1, reductions use regs).
    const float4* src = (const float4*)(d_s + b * LC);
    for (int i = tid; i < LC / 4; i += NT) ((float4*)sh_s)[i] = src[i];
    __syncthreads();

    // register-resident values; invalid -> -1e5 (contributes 0, never max)
    float v[16];
    #pragma unroll
    for (int k = 0; k < 16; k++) {
        int i = tid + k * NT;
        v[k] = (i < len) ? sh_s[i] : -100000.0f;
    }

    // local max and z_sum(0)
    float mx = -100000.0f, sum0 = 0.f;
    #pragma unroll
    for (int k = 0; k < 16; k++) {
        mx = fmaxf(mx, v[k]);
        sum0 += clip01(v[k]);
    }

    // block reduce (max, sum) fused
    {
        #pragma unroll
        for (int off = 16; off; off >>= 1) {
            mx   = fmaxf(mx, __shfl_xor_sync(0xffffffffu, mx, off));
            sum0 += __shfl_xor_sync(0xffffffffu, sum0, off);
        }
        __shared__ float rmx[8], rsm[8];
        if (lane == 0) { rmx[warp] = mx; rsm[warp] = sum0; }
        __syncthreads();
        if (warp == 0) {
            float a = (lane < 8) ? rmx[lane] : -100000.0f;
            float s = (lane < 8) ? rsm[lane] : 0.f;
            #pragma unroll
            for (int off = 4; off; off >>= 1) {
                a = fmaxf(a, __shfl_xor_sync(0xffffffffu, a, off));
                s += __shfl_xor_sync(0xffffffffu, s, off);
            }
            if (lane == 0) { redf[0] = a; redf[1] = s; }
        }
        __syncthreads();
        mx = redf[0]; sum0 = redf[1];
    }

    float tau = 0.f;
    if (sum0 > BUDGETF) {
        float lo = 0.f, hi = mx;
        for (int it = 0; it < 40; it++) {
            float mid = 0.5f * (lo + hi);
            float part = 0.f;
            #pragma unroll
            for (int k = 0; k < 16; k++) part += clip01(v[k] - mid);
            // block reduce sum
            #pragma unroll
            for (int off = 16; off; off >>= 1)
                part += __shfl_xor_sync(0xffffffffu, part, off);
            if (lane == 0) redf[warp] = part;
            __syncthreads();
            if (warp == 0) {
                float x = (lane < 8) ? redf[lane] : 0.f;
                #pragma unroll
                for (int off = 4; off; off >>= 1)
                    x += __shfl_xor_sync(0xffffffffu, x, off);
                if (lane == 0) sh_bc = x;
            }
            __syncthreads();
            float tot = sh_bc;
            if (tot > BUDGETF) lo = mid; else hi = mid;
            __syncthreads();   // redf reuse safety
        }
        tau = 0.5f * (lo + hi);
    }

    // fused gather/scatter into token_z
    int qe = qe_arr[b];
    int clen = len - 1;
    for (int p = tid; p < LC; p += NT) {
        float r;
        if (p < qe) {
            r = 1.f;
        } else {
            int idx = p - qe + 1;                 // >= 1
            r = (idx <= clen) ? clip01(sh_s[idx] - tau) : 0.f;
        }
        out[b * LC + p] = r;
    }
}

// ---------------------------------------------------------------------------
extern "C" void kernel_launch(void* const* d_in, const int* in_sizes, int n_in,
                              void* d_out, int out_size) {
    const float* question = (const float*)d_in[0];  // [B,1,H]
    const float* context  = (const float*)d_in[1];  // [B,LC,H]
    const float* Wq       = (const float*)d_in[2];  // [H,P]
    const float* bq       = (const float*)d_in[3];  // [P]
    const float* Wc       = (const float*)d_in[4];  // [H,P]
    const float* bc       = (const float*)d_in[5];  // [P]
    const int*   maskp    = (const int*)d_in[6];    // [B,LC]
    const int*   qep      = (const int*)d_in[7];    // [B]
    float* out = (float*)d_out;                     // [B,MAXLEN]

    qproj_kernel<<<NB, 512>>>(question, Wq, bq, bc, maskp);
    dim3 gu(NB, 4);
    uproj_kernel<<<gu, 256>>>(Wc);
    score_kernel<<<SCORE_BLOCKS, 256>>>(context);
    budget_kernel<<<NB, 256>>>(qep, out);
}